// round 11
// baseline (speedup 1.0000x reference)
#include <cuda_runtime.h>
#include <cuda_fp16.h>

#define DIM    256
#define LINE   24
#define HEADS  8
#define DHEAD  64
#define INNER  512
#define QKV    1536
#define NROWS  196608
#define NBLK   (NROWS / LINE)   // 8192

// ---------------------------------------------------------------------------
// Scratch (device globals, allocation-free)
// ---------------------------------------------------------------------------
__device__ __half g_xh   [(size_t)NROWS * DIM];    // 100 MB
__device__ __half g_qkvh [(size_t)NROWS * QKV];    // 604 MB  (q | k | v)
__device__ __half g_ih   [(size_t)NROWS * INNER];  // 201 MB
__device__ __half g_wqkvT[QKV * DIM];              // [n,k] K-major
__device__ __half g_woutT[DIM * INNER];            // [n,k] K-major

// ---------------------------------------------------------------------------
// Prep kernels
// ---------------------------------------------------------------------------
__global__ void __launch_bounds__(256) f2h_kernel(
    const float* __restrict__ in, __half* __restrict__ out, int n)
{
    int i = (blockIdx.x * 256 + threadIdx.x) * 4;
    if (i < n) {
        float4 v = *(const float4*)(in + i);
        *(__half2*)(out + i)     = __floats2half2_rn(v.x, v.y);
        *(__half2*)(out + i + 2) = __floats2half2_rn(v.z, v.w);
    }
}
__global__ void __launch_bounds__(256) prep_wqkv(
    const float* __restrict__ Wq, const float* __restrict__ Wkv,
    __half* __restrict__ wT)
{
    int idx = blockIdx.x * 256 + threadIdx.x;     // 1536*256
    int n = idx >> 8, k = idx & 255;
    float v = (n < 512) ? Wq[(size_t)k * 512 + n]
                        : Wkv[(size_t)k * 1024 + (n - 512)];
    wT[idx] = __float2half_rn(v);
}
__global__ void __launch_bounds__(256) prep_wout(
    const float* __restrict__ Wout, __half* __restrict__ wT)
{
    int idx = blockIdx.x * 256 + threadIdx.x;     // 256*512
    int n = idx >> 9, k = idx & 511;
    wT[idx] = __float2half_rn(Wout[(size_t)k * 256 + n]);
}

// ---------------------------------------------------------------------------
// fp16 GEMM: C[M,Ntot] = A[M,K] @ Bt[Ntot,K]^T (+bias)
// CTA tile 128x128, 4 warps (warp tile 64x64), BK=64, 3-stage cp.async,
// m16n8k16 HMMA fp32 accum, both fragments via non-trans ldmatrix.
// ---------------------------------------------------------------------------
#define BM 128
#define BN 128
#define BK 64
#define TS 72                       // half stride (144 B): conflict-free LDSM
#define STAGE_H (BM * TS)           // 9216 halfs per tile per stage
#define GSMEM (3 * 2 * STAGE_H * 2) // 110592 bytes

template<bool HALF_OUT>
__global__ void __launch_bounds__(128, 2) gemm_f16(
    const __half* __restrict__ A, const __half* __restrict__ Bt,
    const float* __restrict__ bias, void* __restrict__ Cout,
    int Ntot, int K)
{
    extern __shared__ __half sh[];
    __half* As = sh;                  // [3][128*72]
    __half* Bs = sh + 3 * STAGE_H;    // [3][128*72]

    const int tid  = threadIdx.x;
    const int lane = tid & 31;
    const int wid  = tid >> 5;
    const int g    = lane >> 2;
    const int tg   = lane & 3;
    const int mBase = blockIdx.y * BM;
    const int nBase = blockIdx.x * BN;
    const int wm = (wid >> 1) * 64;   // 2(M) x 2(N) warps, warp tile 64x64
    const int wn = (wid & 1) * 64;
    const int KC = K >> 6;

    float acc[4][8][4];
    #pragma unroll
    for (int a = 0; a < 4; a++)
        #pragma unroll
        for (int b = 0; b < 8; b++)
            #pragma unroll
            for (int c = 0; c < 4; c++) acc[a][b][c] = 0.f;

    // ldmatrix lane addressing (identical for A and K-major B)
    const int fRow = (lane & 7) + ((lane >> 3) & 1) * 8;
    const int fKo  = ((lane >> 4) & 1) * 8;

    auto stage = [&](int kc, int s) {
        const int k0 = kc * BK;
        __half* Ad = As + s * STAGE_H;
        __half* Bd = Bs + s * STAGE_H;
        #pragma unroll
        for (int i = 0; i < 8; i++) {            // A: 128 rows x 8 x 16B
            int id = tid + i * 128;
            int r = id >> 3, ch = id & 7;
            const __half* src = A + (size_t)(mBase + r) * K + k0 + ch * 8;
            unsigned dst = (unsigned)__cvta_generic_to_shared(Ad + r * TS + ch * 8);
            asm volatile("cp.async.cg.shared.global [%0], [%1], 16;"
                         :: "r"(dst), "l"(src));
        }
        #pragma unroll
        for (int i = 0; i < 8; i++) {            // B: 128 n-rows x 8 x 16B
            int id = tid + i * 128;
            int r = id >> 3, ch = id & 7;
            const __half* src = Bt + (size_t)(nBase + r) * K + k0 + ch * 8;
            unsigned dst = (unsigned)__cvta_generic_to_shared(Bd + r * TS + ch * 8);
            asm volatile("cp.async.cg.shared.global [%0], [%1], 16;"
                         :: "r"(dst), "l"(src));
        }
        asm volatile("cp.async.commit_group;" ::: "memory");
    };

    stage(0, 0);
    if (KC > 1) stage(1, 1);
    if (KC > 2) stage(2, 2);

    for (int c = 0; c < KC; c++) {
        if (c + 3 <= KC)      asm volatile("cp.async.wait_group 2;" ::: "memory");
        else if (c + 2 == KC) asm volatile("cp.async.wait_group 1;" ::: "memory");
        else                  asm volatile("cp.async.wait_group 0;" ::: "memory");
        __syncthreads();

        const int s = c % 3;
        const __half* Ab = As + s * STAGE_H;
        const __half* Bb = Bs + s * STAGE_H;

        #pragma unroll
        for (int kk = 0; kk < BK; kk += 16) {
            unsigned a[4][4], b[4][4];
            #pragma unroll
            for (int mi = 0; mi < 4; mi++) {
                unsigned sa = (unsigned)__cvta_generic_to_shared(
                    Ab + (wm + mi * 16 + fRow) * TS + kk + fKo);
                asm volatile(
                    "ldmatrix.sync.aligned.m8n8.x4.shared.b16 {%0,%1,%2,%3},[%4];"
                    : "=r"(a[mi][0]), "=r"(a[mi][1]), "=r"(a[mi][2]), "=r"(a[mi][3])
                    : "r"(sa));
            }
            #pragma unroll
            for (int gb = 0; gb < 4; gb++) {
                unsigned sb = (unsigned)__cvta_generic_to_shared(
                    Bb + (wn + gb * 16 + fRow) * TS + kk + fKo);
                asm volatile(
                    "ldmatrix.sync.aligned.m8n8.x4.shared.b16 {%0,%1,%2,%3},[%4];"
                    : "=r"(b[gb][0]), "=r"(b[gb][1]), "=r"(b[gb][2]), "=r"(b[gb][3])
                    : "r"(sb));
            }
            #pragma unroll
            for (int mi = 0; mi < 4; mi++)
                #pragma unroll
                for (int ni = 0; ni < 8; ni++) {
                    const int gb = ni >> 1, sel = ni & 1;
                    asm volatile(
                        "mma.sync.aligned.m16n8k16.row.col.f32.f16.f16.f32 "
                        "{%0,%1,%2,%3},{%4,%5,%6,%7},{%8,%9},{%0,%1,%2,%3};"
                        : "+f"(acc[mi][ni][0]), "+f"(acc[mi][ni][1]),
                          "+f"(acc[mi][ni][2]), "+f"(acc[mi][ni][3])
                        : "r"(a[mi][0]), "r"(a[mi][1]), "r"(a[mi][2]), "r"(a[mi][3]),
                          "r"(b[gb][sel]), "r"(b[gb][sel + 2]));
                }
        }
        __syncthreads();
        if (c + 3 < KC) stage(c + 3, s);
    }

    // epilogue
    #pragma unroll
    for (int mi = 0; mi < 4; mi++) {
        int r0 = mBase + wm + mi * 16 + g;
        #pragma unroll
        for (int ni = 0; ni < 8; ni++) {
            int c0 = nBase + wn + ni * 8 + 2 * tg;
            if (HALF_OUT) {
                __half* C = (__half*)Cout;
                *(__half2*)(C + (size_t)r0 * Ntot + c0) =
                    __floats2half2_rn(acc[mi][ni][0], acc[mi][ni][1]);
                *(__half2*)(C + (size_t)(r0 + 8) * Ntot + c0) =
                    __floats2half2_rn(acc[mi][ni][2], acc[mi][ni][3]);
            } else {
                float* C = (float*)Cout;
                float b0 = bias[c0], b1 = bias[c0 + 1];
                C[(size_t)r0 * Ntot + c0]           = acc[mi][ni][0] + b0;
                C[(size_t)r0 * Ntot + c0 + 1]       = acc[mi][ni][1] + b1;
                C[(size_t)(r0 + 8) * Ntot + c0]     = acc[mi][ni][2] + b0;
                C[(size_t)(r0 + 8) * Ntot + c0 + 1] = acc[mi][ni][3] + b1;
            }
        }
    }
}

// ---------------------------------------------------------------------------
// f32x2 packed math helpers
// ---------------------------------------------------------------------------
__device__ __forceinline__ unsigned long long pk2(float a, float b) {
    unsigned long long r;
    asm("mov.b64 %0,{%1,%2};" : "=l"(r) : "f"(a), "f"(b));
    return r;
}
__device__ __forceinline__ unsigned long long fma2(
    unsigned long long a, unsigned long long b, unsigned long long c) {
    unsigned long long d;
    asm("fma.rn.f32x2 %0,%1,%2,%3;" : "=l"(d) : "l"(a), "l"(b), "l"(c));
    return d;
}
__device__ __forceinline__ float2 upk2(unsigned long long a) {
    float2 f;
    asm("mov.b64 {%0,%1},%2;" : "=f"(f.x), "=f"(f.y) : "l"(a));
    return f;
}

// ---------------------------------------------------------------------------
// Attention on fused qkv buffer [row,1536] = [q | k | v]
// ---------------------------------------------------------------------------
#define ATTN_SMEM (HEADS * 2 * LINE * DHEAD * 4)   // 98304 bytes

__global__ void __launch_bounds__(256, 2) attn_f16(
    const __half* __restrict__ qkv, const float* __restrict__ pos,
    __half* __restrict__ inner)
{
    extern __shared__ float sm[];
    const int b    = blockIdx.x;
    const int w    = threadIdx.x >> 5;
    const int lane = threadIdx.x & 31;

    float* ks = sm + w * (2 * LINE * DHEAD);
    float* vs = ks + LINE * DHEAD;

    const __half2* kv2 = (const __half2*)qkv;       // row stride 768 half2
    size_t rbase = (size_t)b * LINE * 768 + (size_t)w * 32;
    #pragma unroll
    for (int t = lane; t < LINE * 32; t += 32) {
        int i = t >> 5, d2 = t & 31;
        float2 kf = __half22float2(kv2[rbase + (size_t)i * 768 + 256 + d2]);
        *(float2*)&ks[i * DHEAD + d2 * 2] = kf;
        float2 vf = __half22float2(kv2[rbase + (size_t)i * 768 + 512 + d2]);
        *(float2*)&vs[i * DHEAD + d2 * 2] = vf;
    }
    __syncwarp();

    if (lane < LINE) {
        unsigned long long qp[32];
        const uint4* q4 = (const uint4*)(qkv + (size_t)(b * LINE + lane) * QKV
                                           + w * DHEAD);
        #pragma unroll
        for (int c = 0; c < 8; c++) {
            uint4 u = q4[c];
            const __half2* hp = (const __half2*)&u;
            #pragma unroll
            for (int h = 0; h < 4; h++) {
                float2 f = __half22float2(hp[h]);
                qp[c * 4 + h] = pk2(f.x, f.y);
            }
        }

        float p[LINE];
        #pragma unroll
        for (int j = 0; j < LINE; j++) {
            const ulonglong2* kr = (const ulonglong2*)(ks + j * DHEAD);
            unsigned long long s0 = 0, s1 = 0, s2 = 0, s3 = 0;
            #pragma unroll
            for (int c = 0; c < 8; c++) {
                ulonglong2 k0 = kr[2 * c], k1 = kr[2 * c + 1];
                s0 = fma2(qp[4 * c + 0], k0.x, s0);
                s1 = fma2(qp[4 * c + 1], k0.y, s1);
                s2 = fma2(qp[4 * c + 2], k1.x, s2);
                s3 = fma2(qp[4 * c + 3], k1.y, s3);
            }
            float2 f0 = upk2(s0), f1 = upk2(s1), f2 = upk2(s2), f3 = upk2(s3);
            p[j] = ((f0.x + f0.y) + (f1.x + f1.y)) +
                   ((f2.x + f2.y) + (f3.x + f3.y));
        }

        const float4* pe4 = (const float4*)(pos + (size_t)w * LINE * LINE
                                              + lane * LINE);
        #pragma unroll
        for (int c = 0; c < 6; c++) {
            float4 pe = pe4[c];
            p[4 * c + 0] = p[4 * c + 0] * 0.125f + pe.x;
            p[4 * c + 1] = p[4 * c + 1] * 0.125f + pe.y;
            p[4 * c + 2] = p[4 * c + 2] * 0.125f + pe.z;
            p[4 * c + 3] = p[4 * c + 3] * 0.125f + pe.w;
        }
        float m = -1e30f;
        #pragma unroll
        for (int j = 0; j < LINE; j++) m = fmaxf(m, p[j]);
        float ssum = 0.f;
        #pragma unroll
        for (int j = 0; j < LINE; j++) { p[j] = __expf(p[j] - m); ssum += p[j]; }
        float inv = 1.f / ssum;
        #pragma unroll
        for (int j = 0; j < LINE; j++) p[j] *= inv;

        __half* og = inner + (size_t)(b * LINE + lane) * INNER + w * DHEAD;
        #pragma unroll
        for (int h2 = 0; h2 < 2; h2++) {
            unsigned long long a[16];
            #pragma unroll
            for (int c = 0; c < 16; c++) a[c] = 0;
            #pragma unroll
            for (int j = 0; j < LINE; j++) {
                unsigned long long pj = pk2(p[j], p[j]);
                const ulonglong2* vr =
                    (const ulonglong2*)(vs + j * DHEAD + h2 * 32);
                #pragma unroll
                for (int c = 0; c < 8; c++) {
                    ulonglong2 vv = vr[c];
                    a[2 * c]     = fma2(pj, vv.x, a[2 * c]);
                    a[2 * c + 1] = fma2(pj, vv.y, a[2 * c + 1]);
                }
            }
            unsigned oh[16];
            #pragma unroll
            for (int c = 0; c < 16; c++) {
                float2 f = upk2(a[c]);
                __half2 h = __floats2half2_rn(f.x, f.y);
                oh[c] = *(unsigned*)&h;
            }
            uint4* o4 = (uint4*)(og + h2 * 32);
            #pragma unroll
            for (int c = 0; c < 4; c++)
                o4[c] = make_uint4(oh[4*c], oh[4*c+1], oh[4*c+2], oh[4*c+3]);
        }
    }
}

// ---------------------------------------------------------------------------
// Launch
// ---------------------------------------------------------------------------
extern "C" void kernel_launch(void* const* d_in, const int* in_sizes, int n_in,
                              void* d_out, int out_size)
{
    (void)in_sizes; (void)n_in; (void)out_size;
    const float* x    = (const float*)d_in[0];
    const float* Wq   = (const float*)d_in[1];
    const float* Wkv  = (const float*)d_in[2];
    const float* Wout = (const float*)d_in[3];
    const float* bout = (const float*)d_in[4];
    const float* pos  = (const float*)d_in[5];
    float* out = (float*)d_out;

    __half *xh, *qkvh, *ih, *wqkvT, *woutT;
    cudaGetSymbolAddress((void**)&xh,    g_xh);
    cudaGetSymbolAddress((void**)&qkvh,  g_qkvh);
    cudaGetSymbolAddress((void**)&ih,    g_ih);
    cudaGetSymbolAddress((void**)&wqkvT, g_wqkvT);
    cudaGetSymbolAddress((void**)&woutT, g_woutT);

    cudaFuncSetAttribute(gemm_f16<true>,
        cudaFuncAttributeMaxDynamicSharedMemorySize, GSMEM);
    cudaFuncSetAttribute(gemm_f16<false>,
        cudaFuncAttributeMaxDynamicSharedMemorySize, GSMEM);
    cudaFuncSetAttribute(attn_f16,
        cudaFuncAttributeMaxDynamicSharedMemorySize, ATTN_SMEM);

    // 0) prep: x -> fp16; weights -> fp16 K-major (transposed, q|k|v fused)
    f2h_kernel<<<(NROWS * DIM) / 4 / 256, 256>>>(x, xh, NROWS * DIM);
    prep_wqkv<<<QKV, 256>>>(Wq, Wkv, wqkvT);
    prep_wout<<<INNER, 256>>>(Wout, woutT);

    // 1) qkv = x @ [Wq|Wk|Wv]   (fp16 out, ldc = 1536)
    gemm_f16<true><<<dim3(QKV / BN, NROWS / BM), 128, GSMEM>>>(
        xh, wqkvT, nullptr, qkvh, QKV, DIM);

    // 2) attention
    attn_f16<<<NBLK, 256, ATTN_SMEM>>>(qkvh, pos, ih);

    // 3) out = inner @ Wout + b  (fp32 out)
    gemm_f16<false><<<dim3(DIM / BN, NROWS / BM), 128, GSMEM>>>(
        ih, woutT, bout, out, DIM, INNER);
}

// round 13
// speedup vs baseline: 1.2656x; 1.2656x over previous
#include <cuda_runtime.h>
#include <cuda_fp16.h>

#define DIM    256
#define LINE   24
#define HEADS  8
#define DHEAD  64
#define INNER  512
#define QKV    1536
#define NROWS  196608
#define NBLK   (NROWS / LINE)   // 8192

// ---------------------------------------------------------------------------
// Scratch (device globals, allocation-free)
// ---------------------------------------------------------------------------
__device__ __half g_xh   [(size_t)NROWS * DIM];    // 100 MB
__device__ __half g_qkvh [(size_t)NROWS * QKV];    // 604 MB  (q | k | v)
__device__ __half g_ih   [(size_t)NROWS * INNER];  // 201 MB
__device__ __half g_wqkvT[QKV * DIM];              // [n,k] K-major
__device__ __half g_woutT[DIM * INNER];            // [n,k] K-major

// ---------------------------------------------------------------------------
// Prep kernels
// ---------------------------------------------------------------------------
__global__ void __launch_bounds__(256) f2h_kernel(
    const float* __restrict__ in, __half* __restrict__ out, int n)
{
    int i = (blockIdx.x * 256 + threadIdx.x) * 4;
    if (i < n) {
        float4 v = *(const float4*)(in + i);
        *(__half2*)(out + i)     = __floats2half2_rn(v.x, v.y);
        *(__half2*)(out + i + 2) = __floats2half2_rn(v.z, v.w);
    }
}
__global__ void __launch_bounds__(256) prep_wqkv(
    const float* __restrict__ Wq, const float* __restrict__ Wkv,
    __half* __restrict__ wT)
{
    int idx = blockIdx.x * 256 + threadIdx.x;     // 1536*256
    int n = idx >> 8, k = idx & 255;
    float v = (n < 512) ? Wq[(size_t)k * 512 + n]
                        : Wkv[(size_t)k * 1024 + (n - 512)];
    wT[idx] = __float2half_rn(v);
}
__global__ void __launch_bounds__(256) prep_wout(
    const float* __restrict__ Wout, __half* __restrict__ wT)
{
    int idx = blockIdx.x * 256 + threadIdx.x;     // 256*512
    int n = idx >> 9, k = idx & 511;
    wT[idx] = __float2half_rn(Wout[(size_t)k * 256 + n]);
}

// ---------------------------------------------------------------------------
// fp16 GEMM (round-10 config: best measured, 634us on qkv).
// CTA 128x128, 8 warps (64x32), BK=64, 3-stage cp.async, K-major B.
// ---------------------------------------------------------------------------
#define BM 128
#define BN 128
#define BK 64
#define TS 72
#define STAGE_H (BM * TS)
#define GSMEM (3 * 2 * STAGE_H * 2)

template<bool HALF_OUT>
__global__ void __launch_bounds__(256) gemm_f16(
    const __half* __restrict__ A, const __half* __restrict__ Bt,
    const float* __restrict__ bias, void* __restrict__ Cout,
    int Ntot, int K)
{
    extern __shared__ __half sh[];
    __half* As = sh;
    __half* Bs = sh + 3 * STAGE_H;

    const int tid  = threadIdx.x;
    const int lane = tid & 31;
    const int wid  = tid >> 5;
    const int g    = lane >> 2;
    const int tg   = lane & 3;
    const int mBase = blockIdx.y * BM;
    const int nBase = blockIdx.x * BN;
    const int wm = (wid >> 2) * 64;
    const int wn = (wid & 3) * 32;
    const int KC = K >> 6;

    float acc[4][4][4];
    #pragma unroll
    for (int a = 0; a < 4; a++)
        #pragma unroll
        for (int b = 0; b < 4; b++)
            #pragma unroll
            for (int c = 0; c < 4; c++) acc[a][b][c] = 0.f;

    const int fRow = (lane & 7) + ((lane >> 3) & 1) * 8;
    const int fKo  = ((lane >> 4) & 1) * 8;

    auto stage = [&](int kc, int s) {
        const int k0 = kc * BK;
        __half* Ad = As + s * STAGE_H;
        __half* Bd = Bs + s * STAGE_H;
        #pragma unroll
        for (int i = 0; i < 4; i++) {
            int id = tid + i * 256;
            int r = id >> 3, ch = id & 7;
            const __half* src = A + (size_t)(mBase + r) * K + k0 + ch * 8;
            unsigned dst = (unsigned)__cvta_generic_to_shared(Ad + r * TS + ch * 8);
            asm volatile("cp.async.cg.shared.global [%0], [%1], 16;"
                         :: "r"(dst), "l"(src));
        }
        #pragma unroll
        for (int i = 0; i < 4; i++) {
            int id = tid + i * 256;
            int r = id >> 3, ch = id & 7;
            const __half* src = Bt + (size_t)(nBase + r) * K + k0 + ch * 8;
            unsigned dst = (unsigned)__cvta_generic_to_shared(Bd + r * TS + ch * 8);
            asm volatile("cp.async.cg.shared.global [%0], [%1], 16;"
                         :: "r"(dst), "l"(src));
        }
        asm volatile("cp.async.commit_group;" ::: "memory");
    };

    stage(0, 0);
    if (KC > 1) stage(1, 1);
    if (KC > 2) stage(2, 2);

    for (int c = 0; c < KC; c++) {
        if (c + 3 <= KC)      asm volatile("cp.async.wait_group 2;" ::: "memory");
        else if (c + 2 == KC) asm volatile("cp.async.wait_group 1;" ::: "memory");
        else                  asm volatile("cp.async.wait_group 0;" ::: "memory");
        __syncthreads();

        const int s = c % 3;
        const __half* Ab = As + s * STAGE_H;
        const __half* Bb = Bs + s * STAGE_H;

        #pragma unroll
        for (int kk = 0; kk < BK; kk += 16) {
            unsigned a[4][4], b[2][4];
            #pragma unroll
            for (int mi = 0; mi < 4; mi++) {
                unsigned sa = (unsigned)__cvta_generic_to_shared(
                    Ab + (wm + mi * 16 + fRow) * TS + kk + fKo);
                asm volatile(
                    "ldmatrix.sync.aligned.m8n8.x4.shared.b16 {%0,%1,%2,%3},[%4];"
                    : "=r"(a[mi][0]), "=r"(a[mi][1]), "=r"(a[mi][2]), "=r"(a[mi][3])
                    : "r"(sa));
            }
            #pragma unroll
            for (int gb = 0; gb < 2; gb++) {
                unsigned sb = (unsigned)__cvta_generic_to_shared(
                    Bb + (wn + gb * 16 + fRow) * TS + kk + fKo);
                asm volatile(
                    "ldmatrix.sync.aligned.m8n8.x4.shared.b16 {%0,%1,%2,%3},[%4];"
                    : "=r"(b[gb][0]), "=r"(b[gb][1]), "=r"(b[gb][2]), "=r"(b[gb][3])
                    : "r"(sb));
            }
            #pragma unroll
            for (int mi = 0; mi < 4; mi++)
                #pragma unroll
                for (int ni = 0; ni < 4; ni++) {
                    const int gb = ni >> 1, sel = ni & 1;
                    asm volatile(
                        "mma.sync.aligned.m16n8k16.row.col.f32.f16.f16.f32 "
                        "{%0,%1,%2,%3},{%4,%5,%6,%7},{%8,%9},{%0,%1,%2,%3};"
                        : "+f"(acc[mi][ni][0]), "+f"(acc[mi][ni][1]),
                          "+f"(acc[mi][ni][2]), "+f"(acc[mi][ni][3])
                        : "r"(a[mi][0]), "r"(a[mi][1]), "r"(a[mi][2]), "r"(a[mi][3]),
                          "r"(b[gb][sel]), "r"(b[gb][sel + 2]));
                }
        }
        __syncthreads();
        if (c + 3 < KC) stage(c + 3, s);
    }

    #pragma unroll
    for (int mi = 0; mi < 4; mi++) {
        int r0 = mBase + wm + mi * 16 + g;
        #pragma unroll
        for (int ni = 0; ni < 4; ni++) {
            int c0 = nBase + wn + ni * 8 + 2 * tg;
            if (HALF_OUT) {
                __half* C = (__half*)Cout;
                *(__half2*)(C + (size_t)r0 * Ntot + c0) =
                    __floats2half2_rn(acc[mi][ni][0], acc[mi][ni][1]);
                *(__half2*)(C + (size_t)(r0 + 8) * Ntot + c0) =
                    __floats2half2_rn(acc[mi][ni][2], acc[mi][ni][3]);
            } else {
                float* C = (float*)Cout;
                float b0 = bias[c0], b1 = bias[c0 + 1];
                C[(size_t)r0 * Ntot + c0]           = acc[mi][ni][0] + b0;
                C[(size_t)r0 * Ntot + c0 + 1]       = acc[mi][ni][1] + b1;
                C[(size_t)(r0 + 8) * Ntot + c0]     = acc[mi][ni][2] + b0;
                C[(size_t)(r0 + 8) * Ntot + c0 + 1] = acc[mi][ni][3] + b1;
            }
        }
    }
}

// ---------------------------------------------------------------------------
// MMA-based attention: warp = (block, head). S=QK^T and O=PV on tensor cores,
// softmax in registers on the accumulator fragment layout.
// smem per head: q,k,v each [32 rows x 72 halfs] (rows 24-31 zero pad).
// ---------------------------------------------------------------------------
#define AT_STRIDE 72
#define AT_MAT    (32 * AT_STRIDE)           // 2304 halfs
#define AT_HEAD   (3 * AT_MAT)
#define ATTN_SMEM (HEADS * AT_HEAD * 2)      // 110592 bytes

__global__ void __launch_bounds__(256, 2) attn_mma(
    const __half* __restrict__ qkv, const float* __restrict__ pos,
    __half* __restrict__ inner)
{
    extern __shared__ __half ash[];
    const int b    = blockIdx.x;
    const int w    = threadIdx.x >> 5;   // head
    const int lane = threadIdx.x & 31;
    const int g    = lane >> 2;
    const int tg   = lane & 3;

    __half* qs = ash + w * AT_HEAD;
    __half* ks = qs + AT_MAT;
    __half* vs = ks + AT_MAT;

    // zero pad rows 24..31 of q,k,v
    #pragma unroll
    for (int m = 0; m < 3; m++) {
        unsigned* pz = (unsigned*)(qs + m * AT_MAT + 24 * AT_STRIDE);
        for (int i = lane; i < (8 * AT_STRIDE) / 2; i += 32) pz[i] = 0u;
    }
    // stage 24 valid rows (q|k|v slices of fused row)
    const __half* gq = qkv + (size_t)b * LINE * QKV + w * DHEAD;
    for (int t = lane; t < 192; t += 32) {
        int r = t >> 3, ch = t & 7;
        size_t off = (size_t)r * QKV + ch * 8;
        *(uint4*)(qs + r * AT_STRIDE + ch * 8) = *(const uint4*)(gq + off);
        *(uint4*)(ks + r * AT_STRIDE + ch * 8) = *(const uint4*)(gq + off + 512);
        *(uint4*)(vs + r * AT_STRIDE + ch * 8) = *(const uint4*)(gq + off + 1024);
    }
    __syncwarp();

    const int fRow = (lane & 7) + ((lane >> 3) & 1) * 8;
    const int fKo  = ((lane >> 4) & 1) * 8;

    // ---- S = Q @ K^T   (M 2x16, N 3x8 used, K 4x16)
    float s[2][3][4];
    #pragma unroll
    for (int mi = 0; mi < 2; mi++)
        #pragma unroll
        for (int nt = 0; nt < 3; nt++)
            #pragma unroll
            for (int c = 0; c < 4; c++) s[mi][nt][c] = 0.f;

    #pragma unroll
    for (int kk = 0; kk < 64; kk += 16) {
        unsigned a[2][4], bk[2][4];
        #pragma unroll
        for (int mi = 0; mi < 2; mi++) {
            unsigned sa = (unsigned)__cvta_generic_to_shared(
                qs + (mi * 16 + fRow) * AT_STRIDE + kk + fKo);
            asm volatile(
                "ldmatrix.sync.aligned.m8n8.x4.shared.b16 {%0,%1,%2,%3},[%4];"
                : "=r"(a[mi][0]), "=r"(a[mi][1]), "=r"(a[mi][2]), "=r"(a[mi][3])
                : "r"(sa));
        }
        #pragma unroll
        for (int gb = 0; gb < 2; gb++) {
            unsigned sb = (unsigned)__cvta_generic_to_shared(
                ks + (gb * 16 + fRow) * AT_STRIDE + kk + fKo);
            asm volatile(
                "ldmatrix.sync.aligned.m8n8.x4.shared.b16 {%0,%1,%2,%3},[%4];"
                : "=r"(bk[gb][0]), "=r"(bk[gb][1]), "=r"(bk[gb][2]), "=r"(bk[gb][3])
                : "r"(sb));
        }
        #pragma unroll
        for (int mi = 0; mi < 2; mi++)
            #pragma unroll
            for (int nt = 0; nt < 3; nt++) {
                const int gb = nt >> 1, sel = nt & 1;
                asm volatile(
                    "mma.sync.aligned.m16n8k16.row.col.f32.f16.f16.f32 "
                    "{%0,%1,%2,%3},{%4,%5,%6,%7},{%8,%9},{%0,%1,%2,%3};"
                    : "+f"(s[mi][nt][0]), "+f"(s[mi][nt][1]),
                      "+f"(s[mi][nt][2]), "+f"(s[mi][nt][3])
                    : "r"(a[mi][0]), "r"(a[mi][1]), "r"(a[mi][2]), "r"(a[mi][3]),
                      "r"(bk[gb][sel]), "r"(bk[gb][sel + 2]));
            }
    }

    // ---- softmax over the 3 valid rows this lane touches: g, g+8, 16+g
    const float* pb = pos + (size_t)w * LINE * LINE;
    float e[3][6];
    const int rows[3] = {g, g + 8, 16 + g};
    #pragma unroll
    for (int rr = 0; rr < 3; rr++) {
        #pragma unroll
        for (int nt = 0; nt < 3; nt++) {
            float v0, v1;
            if (rr == 0)      { v0 = s[0][nt][0]; v1 = s[0][nt][1]; }
            else if (rr == 1) { v0 = s[0][nt][2]; v1 = s[0][nt][3]; }
            else              { v0 = s[1][nt][0]; v1 = s[1][nt][1]; }
            float2 pe = *(const float2*)(pb + rows[rr] * LINE + nt * 8 + 2 * tg);
            e[rr][2 * nt]     = v0 * 0.125f + pe.x;
            e[rr][2 * nt + 1] = v1 * 0.125f + pe.y;
        }
        float mx = e[rr][0];
        #pragma unroll
        for (int j = 1; j < 6; j++) mx = fmaxf(mx, e[rr][j]);
        mx = fmaxf(mx, __shfl_xor_sync(0xFFFFFFFF, mx, 1));
        mx = fmaxf(mx, __shfl_xor_sync(0xFFFFFFFF, mx, 2));
        float sum = 0.f;
        #pragma unroll
        for (int j = 0; j < 6; j++) { e[rr][j] = __expf(e[rr][j] - mx); sum += e[rr][j]; }
        sum += __shfl_xor_sync(0xFFFFFFFF, sum, 1);
        sum += __shfl_xor_sync(0xFFFFFFFF, sum, 2);
        float inv = 1.f / sum;
        #pragma unroll
        for (int j = 0; j < 6; j++) e[rr][j] *= inv;
    }

    // ---- pack P into fp16 A-fragments. Pad rows (24-31) and cols (24-31) = 0.
    unsigned p[3][3];
    #pragma unroll
    for (int rr = 0; rr < 3; rr++)
        #pragma unroll
        for (int nt = 0; nt < 3; nt++) {
            __half2 h = __floats2half2_rn(e[rr][2 * nt], e[rr][2 * nt + 1]);
            p[rr][nt] = *(unsigned*)&h;
        }
    unsigned Pf[2][2][4];
    Pf[0][0][0] = p[0][0]; Pf[0][0][1] = p[1][0]; Pf[0][0][2] = p[0][1]; Pf[0][0][3] = p[1][1];
    Pf[0][1][0] = p[0][2]; Pf[0][1][1] = p[1][2]; Pf[0][1][2] = 0;       Pf[0][1][3] = 0;
    Pf[1][0][0] = p[2][0]; Pf[1][0][1] = 0;       Pf[1][0][2] = p[2][1]; Pf[1][0][3] = 0;
    Pf[1][1][0] = p[2][2]; Pf[1][1][1] = 0;       Pf[1][1][2] = 0;       Pf[1][1][3] = 0;

    // ---- O = P @ V, two 32-col halves
    __half* ob = inner + (size_t)(b * LINE) * INNER + w * DHEAD;
    #pragma unroll
    for (int h2 = 0; h2 < 2; h2++) {
        unsigned vb[2][2][4];
        #pragma unroll
        for (int kt = 0; kt < 2; kt++)
            #pragma unroll
            for (int nb = 0; nb < 2; nb++) {
                unsigned sv = (unsigned)__cvta_generic_to_shared(
                    vs + (kt * 16 + fRow) * AT_STRIDE + h2 * 32 + nb * 16 + fKo);
                asm volatile(
                    "ldmatrix.sync.aligned.m8n8.x4.trans.shared.b16 {%0,%1,%2,%3},[%4];"
                    : "=r"(vb[kt][nb][0]), "=r"(vb[kt][nb][1]),
                      "=r"(vb[kt][nb][2]), "=r"(vb[kt][nb][3])
                    : "r"(sv));
            }
        float o[2][4][4];
        #pragma unroll
        for (int mi = 0; mi < 2; mi++)
            #pragma unroll
            for (int n8 = 0; n8 < 4; n8++)
                #pragma unroll
                for (int c = 0; c < 4; c++) o[mi][n8][c] = 0.f;

        #pragma unroll
        for (int mi = 0; mi < 2; mi++)
            #pragma unroll
            for (int n8 = 0; n8 < 4; n8++) {
                const int nb = n8 >> 1, s2 = (n8 & 1) * 2;
                #pragma unroll
                for (int kt = 0; kt < 2; kt++) {
                    asm volatile(
                        "mma.sync.aligned.m16n8k16.row.col.f32.f16.f16.f32 "
                        "{%0,%1,%2,%3},{%4,%5,%6,%7},{%8,%9},{%0,%1,%2,%3};"
                        : "+f"(o[mi][n8][0]), "+f"(o[mi][n8][1]),
                          "+f"(o[mi][n8][2]), "+f"(o[mi][n8][3])
                        : "r"(Pf[mi][kt][0]), "r"(Pf[mi][kt][1]),
                          "r"(Pf[mi][kt][2]), "r"(Pf[mi][kt][3]),
                          "r"(vb[kt][nb][s2]), "r"(vb[kt][nb][s2 + 1]));
                }
            }

        #pragma unroll
        for (int mi = 0; mi < 2; mi++)
            #pragma unroll
            for (int n8 = 0; n8 < 4; n8++) {
                int r0 = mi * 16 + g;
                int c0 = h2 * 32 + n8 * 8 + 2 * tg;
                *(__half2*)(ob + (size_t)r0 * INNER + c0) =
                    __floats2half2_rn(o[mi][n8][0], o[mi][n8][1]);
                if (mi == 0)
                    *(__half2*)(ob + (size_t)(r0 + 8) * INNER + c0) =
                        __floats2half2_rn(o[mi][n8][2], o[mi][n8][3]);
            }
    }
}

// ---------------------------------------------------------------------------
// Launch
// ---------------------------------------------------------------------------
extern "C" void kernel_launch(void* const* d_in, const int* in_sizes, int n_in,
                              void* d_out, int out_size)
{
    (void)in_sizes; (void)n_in; (void)out_size;
    const float* x    = (const float*)d_in[0];
    const float* Wq   = (const float*)d_in[1];
    const float* Wkv  = (const float*)d_in[2];
    const float* Wout = (const float*)d_in[3];
    const float* bout = (const float*)d_in[4];
    const float* pos  = (const float*)d_in[5];
    float* out = (float*)d_out;

    __half *xh, *qkvh, *ih, *wqkvT, *woutT;
    cudaGetSymbolAddress((void**)&xh,    g_xh);
    cudaGetSymbolAddress((void**)&qkvh,  g_qkvh);
    cudaGetSymbolAddress((void**)&ih,    g_ih);
    cudaGetSymbolAddress((void**)&wqkvT, g_wqkvT);
    cudaGetSymbolAddress((void**)&woutT, g_woutT);

    cudaFuncSetAttribute(gemm_f16<true>,
        cudaFuncAttributeMaxDynamicSharedMemorySize, GSMEM);
    cudaFuncSetAttribute(gemm_f16<false>,
        cudaFuncAttributeMaxDynamicSharedMemorySize, GSMEM);
    cudaFuncSetAttribute(attn_mma,
        cudaFuncAttributeMaxDynamicSharedMemorySize, ATTN_SMEM);

    // 0) prep
    f2h_kernel<<<(NROWS * DIM) / 4 / 256, 256>>>(x, xh, NROWS * DIM);
    prep_wqkv<<<QKV, 256>>>(Wq, Wkv, wqkvT);
    prep_wout<<<INNER, 256>>>(Wout, woutT);

    // 1) qkv = x @ [Wq|Wk|Wv]   (fp16 out, ldc = 1536)
    gemm_f16<true><<<dim3(QKV / BN, NROWS / BM), 256, GSMEM>>>(
        xh, wqkvT, nullptr, qkvh, QKV, DIM);

    // 2) attention (tensor-core)
    attn_mma<<<NBLK, 256, ATTN_SMEM>>>(qkvh, pos, ih);

    // 3) out = inner @ Wout + b  (fp32 out)
    gemm_f16<false><<<dim3(DIM / BN, NROWS / BM), 256, GSMEM>>>(
        ih, woutT, bout, out, DIM, INNER);
}